// round 1
// baseline (speedup 1.0000x reference)
#include <cuda_runtime.h>
#include <math.h>

#define BN 16
#define UPD 512
#define NPIX (UPD*UPD)
#define PATCH 120
#define NM 4

// ---------------- static device scratch (no runtime allocation) ----------------
__device__ float g_inv[3*BN*6];              // inverse thetas: [which][b][6]
__device__ float g_bufA[BN*NPIX];            // pred_trans
__device__ float g_bufB[BN*NPIX];            // pred_rot
__device__ float g_rm2[NM*BN*NPIX];          // mask after g2 sample
__device__ float g_part1[NM*BN*64*2];        // partial sums (new, mask)
__device__ float g_part3[NM*BN*64*3];        // partial sums (tot, sx, sy)
__device__ float g_thr[NM*BN];               // per (j,b) threshold
__device__ float g_patch[BN*PATCH*PATCH];    // revise patch snapshot

// ---------------- helpers ----------------
__device__ __forceinline__ float bilin_sample(const float* __restrict__ s,
                                              float gx, float gy, int H, int W) {
    // torch grid_sample: bilinear, zero padding, align_corners=False
    float x = ((gx + 1.0f) * (float)W - 1.0f) * 0.5f;
    float y = ((gy + 1.0f) * (float)H - 1.0f) * 0.5f;
    float xf = floorf(x), yf = floorf(y);
    int x0 = (int)xf, y0 = (int)yf;
    float wx = x - xf, wy = y - yf;
    int x1 = x0 + 1, y1 = y0 + 1;
    bool xi0 = (x0 >= 0) && (x0 < W);
    bool xi1 = (x1 >= 0) && (x1 < W);
    bool yi0 = (y0 >= 0) && (y0 < H);
    bool yi1 = (y1 >= 0) && (y1 < H);
    float v00 = 0.f, v01 = 0.f, v10 = 0.f, v11 = 0.f;
    if (yi0) {
        const float* row = s + y0 * W;
        if (xi0) v00 = row[x0];
        if (xi1) v01 = row[x1];
    }
    if (yi1) {
        const float* row = s + y1 * W;
        if (xi0) v10 = row[x0];
        if (xi1) v11 = row[x1];
    }
    return (1.f - wx) * (1.f - wy) * v00 + wx * (1.f - wy) * v01
         + (1.f - wx) * wy * v10 + wx * wy * v11;
}

// ---------------- K0: 2x3 affine inverses ----------------
__global__ void k_inv(const float* __restrict__ sc, const float* __restrict__ ro,
                      const float* __restrict__ tr) {
    int t = threadIdx.x;
    if (t >= 3 * BN) return;
    int w = t / BN, b = t % BN;
    const float* src = (w == 0) ? sc : ((w == 1) ? ro : tr);
    const float* m = src + b * 6;
    float a = m[0], bb = m[1], c = m[2], d = m[3], e = m[4], f = m[5];
    float det = a * e - bb * d;
    float ia = e / det, ib = -bb / det, id = -d / det, ie = a / det;
    float ic  = -(ia * c + ib * f);
    float iff = -(id * c + ie * f);
    float* o = g_inv + t * 6;
    o[0] = ia; o[1] = ib; o[2] = ic; o[3] = id; o[4] = ie; o[5] = iff;
}

// ---------------- K1: jax.image.resize linear (clamped bilinear 128->512) ----------------
__global__ void k_resize(const float* __restrict__ base, float* __restrict__ out) {
    int idx = blockIdx.x * blockDim.x + threadIdx.x;
    if (idx >= BN * NPIX) return;
    int b = idx / NPIX, r = idx - b * NPIX;
    int i = r >> 9, j = r & 511;
    float fy = (i + 0.5f) * 0.25f - 0.5f;
    float fx = (j + 0.5f) * 0.25f - 0.5f;
    fy = fminf(fmaxf(fy, 0.f), 127.f);
    fx = fminf(fmaxf(fx, 0.f), 127.f);
    int y0 = (int)fy, x0 = (int)fx;
    float wy = fy - (float)y0, wx = fx - (float)x0;
    int y1 = min(y0 + 1, 127), x1 = min(x0 + 1, 127);
    const float* p = base + b * 128 * 128;
    float v00 = p[y0 * 128 + x0], v01 = p[y0 * 128 + x1];
    float v10 = p[y1 * 128 + x0], v11 = p[y1 * 128 + x1];
    out[idx] = (1.f - wy) * ((1.f - wx) * v00 + wx * v01)
             + wy * ((1.f - wx) * v10 + wx * v11);
}

// ---------------- image warp chain ----------------
__device__ __forceinline__ void warp_coord(int i, int j, const float* th,
                                           float& gx, float& gy) {
    float X = (float)(2 * j + 1) / 512.0f - 1.0f;
    float Y = (float)(2 * i + 1) / 512.0f - 1.0f;
    gx = th[0] * X + th[1] * Y + th[2];
    gy = th[3] * X + th[4] * Y + th[5];
}

__global__ void k_warp_a(const float* __restrict__ src) {   // seg0 -> g_bufA, theta=inv(translation)
    int idx = blockIdx.x * blockDim.x + threadIdx.x;
    if (idx >= BN * NPIX) return;
    int b = idx / NPIX, r = idx - b * NPIX;
    const float* th = g_inv + (2 * BN + b) * 6;
    float gx, gy; warp_coord(r >> 9, r & 511, th, gx, gy);
    g_bufA[idx] = bilin_sample(src + b * NPIX, gx, gy, UPD, UPD);
}

__global__ void k_warp_b() {                                 // g_bufA -> g_bufB, theta=inv(rotation)
    int idx = blockIdx.x * blockDim.x + threadIdx.x;
    if (idx >= BN * NPIX) return;
    int b = idx / NPIX, r = idx - b * NPIX;
    const float* th = g_inv + (1 * BN + b) * 6;
    float gx, gy; warp_coord(r >> 9, r & 511, th, gx, gy);
    g_bufB[idx] = bilin_sample(g_bufA + b * NPIX, gx, gy, UPD, UPD);
}

__global__ void k_warp_c(float* __restrict__ dst, float* __restrict__ dst2) { // -> seg1 & seg2, theta=inv(shear)
    int idx = blockIdx.x * blockDim.x + threadIdx.x;
    if (idx >= BN * NPIX) return;
    int b = idx / NPIX, r = idx - b * NPIX;
    const float* th = g_inv + (0 * BN + b) * 6;
    float gx, gy; warp_coord(r >> 9, r & 511, th, gx, gy);
    float v = bilin_sample(g_bufB + b * NPIX, gx, gy, UPD, UPD);
    dst[idx] = v;
    dst2[idx] = v;
}

// ---------------- mask chain ----------------
__global__ void k_mask1(const float* __restrict__ masks) {   // mask_j -> g_rm2 via g2
    int idx = blockIdx.x * blockDim.x + threadIdx.x;
    if (idx >= NM * BN * NPIX) return;
    int jb = idx / NPIX, r = idx - jb * NPIX;
    int j = jb / BN, b = jb - j * BN;
    const float* th = g_inv + (1 * BN + b) * 6;
    float gx, gy; warp_coord(r >> 9, r & 511, th, gx, gy);
    g_rm2[idx] = bilin_sample(masks + j * NPIX, gx, gy, UPD, UPD);
}

__global__ void k_mask2(float* __restrict__ out) {           // g_rm2 -> masks_rot via g1, >=0.5
    int idx = blockIdx.x * blockDim.x + threadIdx.x;
    if (idx >= NM * BN * NPIX) return;
    int jb = idx / NPIX, r = idx - jb * NPIX;
    int b = jb % BN;
    const float* th = g_inv + (0 * BN + b) * 6;
    float gx, gy; warp_coord(r >> 9, r & 511, th, gx, gy);
    float v = bilin_sample(g_rm2 + jb * NPIX, gx, gy, UPD, UPD);
    out[idx] = (v >= 0.5f) ? 1.0f : 0.0f;
}

// ---------------- COM reductions (deterministic block trees) ----------------
__global__ void k_p1(const float* __restrict__ pin, const float* __restrict__ mrot) {
    int chunk = blockIdx.x, b = blockIdx.y, j = blockIdx.z;
    const float* img = pin + b * NPIX;
    const float* m = mrot + (j * BN + b) * NPIX;
    int base = chunk * 4096;
    float sn = 0.f, sm = 0.f;
    for (int k = threadIdx.x; k < 4096; k += 512) {
        float mv = m[base + k];
        sn += img[base + k] * mv;
        sm += mv;
    }
    __shared__ float sh1[512], sh2[512];
    sh1[threadIdx.x] = sn; sh2[threadIdx.x] = sm;
    __syncthreads();
    for (int s = 256; s > 0; s >>= 1) {
        if (threadIdx.x < s) {
            sh1[threadIdx.x] += sh1[threadIdx.x + s];
            sh2[threadIdx.x] += sh2[threadIdx.x + s];
        }
        __syncthreads();
    }
    if (threadIdx.x == 0) {
        int o = ((j * BN + b) * 64 + chunk) * 2;
        g_part1[o] = sh1[0]; g_part1[o + 1] = sh2[0];
    }
}

__global__ void k_p2() {
    int t = threadIdx.x;
    if (t >= NM * BN) return;
    float sn = 0.f, sm = 0.f;
    for (int k = 0; k < 64; k++) {
        sn += g_part1[(t * 64 + k) * 2];
        sm += g_part1[(t * 64 + k) * 2 + 1];
    }
    float msum = fmaxf(sm, 1.0f);
    g_thr[t] = (sn / msum) * 1.5f;
}

__global__ void k_p3(const float* __restrict__ pin, const float* __restrict__ mrot) {
    int chunk = blockIdx.x, b = blockIdx.y, j = blockIdx.z;
    const float* img = pin + b * NPIX;
    const float* m = mrot + (j * BN + b) * NPIX;
    float thr = g_thr[j * BN + b];
    int base = chunk * 4096;
    float st = 0.f, sx = 0.f, sy = 0.f;
    for (int k = threadIdx.x; k < 4096; k += 512) {
        int g = base + k;
        float nv = img[g] * m[g];
        float w = (nv > thr) ? nv : 0.f;
        st += w;
        sx += w * (float)(g >> 9);   // row index
        sy += w * (float)(g & 511);  // col index
    }
    __shared__ float sh1[512], sh2[512], sh3[512];
    sh1[threadIdx.x] = st; sh2[threadIdx.x] = sx; sh3[threadIdx.x] = sy;
    __syncthreads();
    for (int s = 256; s > 0; s >>= 1) {
        if (threadIdx.x < s) {
            sh1[threadIdx.x] += sh1[threadIdx.x + s];
            sh2[threadIdx.x] += sh2[threadIdx.x + s];
            sh3[threadIdx.x] += sh3[threadIdx.x + s];
        }
        __syncthreads();
    }
    if (threadIdx.x == 0) {
        int o = ((j * BN + b) * 64 + chunk) * 3;
        g_part3[o] = sh1[0]; g_part3[o + 1] = sh2[0]; g_part3[o + 2] = sh3[0];
    }
}

// ---------------- revise (one block per batch item; sequential over j via launches) ----------------
__global__ void k_revise(float* __restrict__ rev, const float* __restrict__ adj, int j) {
    int b = blockIdx.x;
    int tid = threadIdx.x;
    __shared__ float red[64 * 3];
    __shared__ int sh_xy[2];
    if (tid < 64) {
        int o = ((j * BN + b) * 64 + tid) * 3;
        red[tid * 3 + 0] = g_part3[o];
        red[tid * 3 + 1] = g_part3[o + 1];
        red[tid * 3 + 2] = g_part3[o + 2];
    }
    __syncthreads();
    if (tid == 0) {
        float tot = 0.f, sx = 0.f, sy = 0.f;
        for (int k = 0; k < 64; k++) {
            tot += red[k * 3]; sx += red[k * 3 + 1]; sy += red[k * 3 + 2];
        }
        tot += 1e-8f;
        float cx = sx / tot, cy = sy / tot;          // cx = row center, cy = col center
        int x0 = __float2int_rn(cx) - 60;            // round half to even (matches jnp.round)
        int y0 = __float2int_rn(cy) - 60;
        x0 = min(max(x0, 0), UPD - PATCH);           // dynamic_slice clamping
        y0 = min(max(y0, 0), UPD - PATCH);
        sh_xy[0] = x0; sh_xy[1] = y0;
    }
    __syncthreads();
    int x0 = sh_xy[0], y0 = sh_xy[1];
    float a = adj[b];
    float* img = rev + b * NPIX;
    float* patch = g_patch + b * PATCH * PATCH;
    // snapshot patch (with dot-circle division, pare_reverse=True)
    for (int t = tid; t < PATCH * PATCH; t += blockDim.x) {
        int p = t / PATCH, q = t - p * PATCH;
        float v = img[(x0 + p) * UPD + (y0 + q)];
        int dp = p - 60, dq = q - 60;
        if (dp * dp + dq * dq <= 16) v = v / a;
        patch[t] = v;
    }
    __syncthreads();
    const float* th = g_inv + b * 6;  // inv(scaler_shear)
    for (int t = tid; t < PATCH * PATCH; t += blockDim.x) {
        int p = t / PATCH, q = t - p * PATCH;
        float X = (float)(2 * q + 1) / 120.0f - 1.0f;
        float Y = (float)(2 * p + 1) / 120.0f - 1.0f;
        float gx = th[0] * X + th[1] * Y + th[2];
        float gy = th[3] * X + th[4] * Y + th[5];
        float v = bilin_sample(patch, gx, gy, PATCH, PATCH);
        img[(x0 + p) * UPD + (y0 + q)] = v;
    }
}

// ---------------- launch ----------------
extern "C" void kernel_launch(void* const* d_in, const int* in_sizes, int n_in,
                              void* d_out, int out_size) {
    const float* base  = (const float*)d_in[0];  // (16,1,128,128)
    const float* sc    = (const float*)d_in[1];  // (16,2,3)
    const float* ro    = (const float*)d_in[2];  // (16,2,3)
    const float* tr    = (const float*)d_in[3];  // (16,2,3)
    const float* adj   = (const float*)d_in[4];  // (16,)
    const float* masks = (const float*)d_in[5];  // (4,512,512)
    float* out = (float*)d_out;
    float* seg0 = out;                 // base_inp    (16,1,512,512)
    float* seg1 = out + (size_t)BN * NPIX;       // pred_input
    float* seg2 = out + (size_t)2 * BN * NPIX;   // pred_revise
    float* seg3 = out + (size_t)3 * BN * NPIX;   // masks_rot (4,16,512,512) as 0/1

    const int TB = 256;
    int nblk_img = (BN * NPIX + TB - 1) / TB;
    int nblk_msk = (NM * BN * NPIX + TB - 1) / TB;

    k_inv<<<1, 64>>>(sc, ro, tr);
    k_resize<<<nblk_img, TB>>>(base, seg0);
    k_warp_a<<<nblk_img, TB>>>(seg0);
    k_warp_b<<<nblk_img, TB>>>();
    k_warp_c<<<nblk_img, TB>>>(seg1, seg2);
    k_mask1<<<nblk_msk, TB>>>(masks);
    k_mask2<<<nblk_msk, TB>>>(seg3);
    k_p1<<<dim3(64, BN, NM), 512>>>(seg1, seg3);
    k_p2<<<1, 64>>>();
    k_p3<<<dim3(64, BN, NM), 512>>>(seg1, seg3);
    for (int j = 0; j < NM; j++) {
        k_revise<<<BN, 512>>>(seg2, adj, j);
    }
}